// round 1
// baseline (speedup 1.0000x reference)
#include <cuda_runtime.h>
#include <cstdint>
#include <math.h>

#define NTOK 4096
#define HDIM 768
#define FDIM 3072
#define ENUM 6
#define NSLOT (NTOK * 2)

// ---------------- device scratch (no allocations allowed) ----------------
__device__ int   g_counts[ENUM];
__device__ int   g_offsets[ENUM + 1];
__device__ int   g_fill[ENUM];
__device__ int   g_tk_idx[NSLOT];
__device__ float g_tk_w[NSLOT];
__device__ int   g_slot_tok[NSLOT];
__device__ float g_slot_w[NSLOT];
__device__ float g_hmid[(size_t)NSLOT * FDIM];   // ~100 MB mid activations

// ---------------- helpers ----------------
__device__ __forceinline__ uint32_t f2tf(float x) {
    uint32_t r;
    asm("cvt.rna.tf32.f32 %0, %1;" : "=r"(r) : "f"(x));
    return r;
}

__device__ __forceinline__ float gelu_exact(float x) {
    return 0.5f * x * (1.0f + erff(x * 0.7071067811865476f));
}

__device__ __forceinline__ void mma_tf32(float* c, const uint32_t* a, const uint32_t* b) {
    asm volatile(
        "mma.sync.aligned.m16n8k8.row.col.f32.tf32.tf32.f32 "
        "{%0,%1,%2,%3}, {%4,%5,%6,%7}, {%8,%9}, {%0,%1,%2,%3};\n"
        : "+f"(c[0]), "+f"(c[1]), "+f"(c[2]), "+f"(c[3])
        : "r"(a[0]), "r"(a[1]), "r"(a[2]), "r"(a[3]), "r"(b[0]), "r"(b[1]));
}

// ---------------- kernel: zero output + routing counters ----------------
__global__ void zero_kernel(float* __restrict__ out) {
    int i = blockIdx.x * blockDim.x + threadIdx.x;
    if (i < NTOK * HDIM) out[i] = 0.0f;
    if (i < ENUM) { g_counts[i] = 0; g_fill[i] = 0; }
}

// ---------------- kernel: gate scores + top-2 + softmax + counts ----------------
__global__ void gate_kernel(const float* __restrict__ x,
                            const float* __restrict__ gw,
                            const float* __restrict__ gb) {
    const int warp = threadIdx.x >> 5;
    const int lane = threadIdx.x & 31;
    const int tok = blockIdx.x * 8 + warp;
    if (tok >= NTOK) return;

    float acc[ENUM];
#pragma unroll
    for (int e = 0; e < ENUM; ++e) acc[e] = 0.0f;

    const float* xr = x + (size_t)tok * HDIM;
    for (int h = lane; h < HDIM; h += 32) {
        float xv = xr[h];
#pragma unroll
        for (int e = 0; e < ENUM; ++e) acc[e] += xv * gw[h * ENUM + e];
    }
#pragma unroll
    for (int e = 0; e < ENUM; ++e) {
#pragma unroll
        for (int off = 16; off > 0; off >>= 1)
            acc[e] += __shfl_xor_sync(0xffffffffu, acc[e], off);
    }
    if (lane == 0) {
        float best = -1e30f, sec = -1e30f;
        int bi = 0, si = 0;
#pragma unroll
        for (int e = 0; e < ENUM; ++e) {
            float s = acc[e] + gb[e];
            if (s > best) { sec = best; si = bi; best = s; bi = e; }
            else if (s > sec) { sec = s; si = e; }
        }
        float r = expf(sec - best);
        float inv = 1.0f / (1.0f + r);
        g_tk_idx[tok * 2]     = bi;
        g_tk_idx[tok * 2 + 1] = si;
        g_tk_w[tok * 2]       = inv;
        g_tk_w[tok * 2 + 1]   = r * inv;
        atomicAdd(&g_counts[bi], 1);
        atomicAdd(&g_counts[si], 1);
    }
}

// ---------------- kernel: tiny exclusive scan over 6 experts ----------------
__global__ void scan_kernel() {
    if (threadIdx.x == 0 && blockIdx.x == 0) {
        int o = 0;
#pragma unroll
        for (int e = 0; e < ENUM; ++e) { g_offsets[e] = o; o += g_counts[e]; }
        g_offsets[ENUM] = o;
    }
}

// ---------------- kernel: scatter tokens into per-expert buckets ----------------
__global__ void scatter_kernel() {
    int n = blockIdx.x * blockDim.x + threadIdx.x;
    if (n >= NTOK) return;
#pragma unroll
    for (int k = 0; k < 2; ++k) {
        int e = g_tk_idx[n * 2 + k];
        int pos = g_offsets[e] + atomicAdd(&g_fill[e], 1);
        g_slot_tok[pos] = n;
        g_slot_w[pos]   = g_tk_w[n * 2 + k];
    }
}

// ---------------- grouped GEMM (tf32 mma), PHASE 1: gelu(X@W1+b1) -> hmid
//                                  PHASE 2: w * (hmid@W2+b2) -> atomicAdd out
template <int PHASE>
__global__ void __launch_bounds__(256) moe_gemm(const float* __restrict__ X,
                                                const float* __restrict__ W,
                                                const float* __restrict__ bias,
                                                float* __restrict__ out) {
    constexpr int KDIM = (PHASE == 1) ? HDIM : FDIM;
    constexpr int LDB  = (PHASE == 1) ? FDIM : HDIM;
    constexpr int KT   = KDIM / 32;

    const int e    = blockIdx.z;
    const int base = g_offsets[e];
    const int cnt  = g_offsets[e + 1] - base;
    const int m0   = blockIdx.y * 128;
    if (m0 >= cnt) return;
    const int n0 = blockIdx.x * 128;

    const float* Bm = W + (size_t)e * KDIM * LDB;

    __shared__ uint32_t As[128 * 36];  // [m][k] stride 36 -> conflict-free frag LDS
    __shared__ uint32_t Bs[32 * 136];  // [k][n] stride 136 -> conflict-free frag LDS

    const int tid = threadIdx.x;
    const int ar = tid >> 3;          // 0..31  (A: 32 rows / pass)
    const int ac = (tid & 7) << 2;    // col*4
    const int br = tid >> 5;          // 0..7   (B: 8 rows / pass)
    const int bc = (tid & 31) << 2;

    // resolve A row pointers once (gathered for PHASE 1, contiguous for PHASE 2)
    const float* arow[4];
#pragma unroll
    for (int p = 0; p < 4; ++p) {
        int r = m0 + p * 32 + ar;
        if (r < cnt) {
            if (PHASE == 1) arow[p] = X + (size_t)g_slot_tok[base + r] * HDIM;
            else            arow[p] = g_hmid + (size_t)(base + r) * FDIM;
        } else arow[p] = nullptr;
    }

    float4 aReg[4], bReg[4];
    auto load_tile = [&](int k0) {
#pragma unroll
        for (int p = 0; p < 4; ++p) {
            aReg[p] = arow[p] ? *(const float4*)(arow[p] + k0 + ac)
                              : make_float4(0.f, 0.f, 0.f, 0.f);
            bReg[p] = *(const float4*)(Bm + (size_t)(k0 + p * 8 + br) * LDB + n0 + bc);
        }
    };
    auto store_tile = [&]() {
#pragma unroll
        for (int p = 0; p < 4; ++p) {
            *(uint4*)&As[(p * 32 + ar) * 36 + ac] =
                make_uint4(f2tf(aReg[p].x), f2tf(aReg[p].y), f2tf(aReg[p].z), f2tf(aReg[p].w));
            *(uint4*)&Bs[(p * 8 + br) * 136 + bc] =
                make_uint4(f2tf(bReg[p].x), f2tf(bReg[p].y), f2tf(bReg[p].z), f2tf(bReg[p].w));
        }
    };

    load_tile(0);
    store_tile();
    __syncthreads();

    const int warp = tid >> 5, lane = tid & 31;
    const int wm = (warp >> 2) * 64;
    const int wn = (warp & 3) * 32;
    const int g = lane >> 2, t = lane & 3;

    float acc[4][4][4];
#pragma unroll
    for (int mf = 0; mf < 4; ++mf)
#pragma unroll
        for (int nf = 0; nf < 4; ++nf)
#pragma unroll
            for (int c = 0; c < 4; ++c) acc[mf][nf][c] = 0.0f;

    for (int kt = 0; kt < KT; ++kt) {
        if (kt + 1 < KT) load_tile((kt + 1) * 32);  // prefetch next tile into regs

#pragma unroll
        for (int s = 0; s < 4; ++s) {
            uint32_t af[4][4];
#pragma unroll
            for (int mf = 0; mf < 4; ++mf) {
                const uint32_t* Ap = &As[(wm + mf * 16 + g) * 36 + s * 8 + t];
                af[mf][0] = Ap[0];
                af[mf][1] = Ap[8 * 36];
                af[mf][2] = Ap[4];
                af[mf][3] = Ap[8 * 36 + 4];
            }
            uint32_t bf[4][2];
#pragma unroll
            for (int nf = 0; nf < 4; ++nf) {
                bf[nf][0] = Bs[(s * 8 + t) * 136 + wn + nf * 8 + g];
                bf[nf][1] = Bs[(s * 8 + t + 4) * 136 + wn + nf * 8 + g];
            }
#pragma unroll
            for (int mf = 0; mf < 4; ++mf)
#pragma unroll
                for (int nf = 0; nf < 4; ++nf)
                    mma_tf32(acc[mf][nf], af[mf], bf[nf]);
        }
        __syncthreads();
        if (kt + 1 < KT) {
            store_tile();
            __syncthreads();
        }
    }

    // -------- epilogue --------
    const float* bv = bias + (size_t)e * LDB;
#pragma unroll
    for (int mf = 0; mf < 4; ++mf) {
        int rl = wm + mf * 16 + g;
#pragma unroll
        for (int nf = 0; nf < 4; ++nf) {
            int col = n0 + wn + nf * 8 + 2 * t;
            float bb0 = bv[col], bb1 = bv[col + 1];
            if (m0 + rl < cnt) {
                if (PHASE == 1) {
                    size_t o = (size_t)(base + m0 + rl) * FDIM + col;
                    g_hmid[o]     = gelu_exact(acc[mf][nf][0] + bb0);
                    g_hmid[o + 1] = gelu_exact(acc[mf][nf][1] + bb1);
                } else {
                    int slot = base + m0 + rl;
                    int tok = g_slot_tok[slot];
                    float w = g_slot_w[slot];
                    atomicAdd(&out[(size_t)tok * HDIM + col],     w * (acc[mf][nf][0] + bb0));
                    atomicAdd(&out[(size_t)tok * HDIM + col + 1], w * (acc[mf][nf][1] + bb1));
                }
            }
            if (m0 + rl + 8 < cnt) {
                if (PHASE == 1) {
                    size_t o = (size_t)(base + m0 + rl + 8) * FDIM + col;
                    g_hmid[o]     = gelu_exact(acc[mf][nf][2] + bb0);
                    g_hmid[o + 1] = gelu_exact(acc[mf][nf][3] + bb1);
                } else {
                    int slot = base + m0 + rl + 8;
                    int tok = g_slot_tok[slot];
                    float w = g_slot_w[slot];
                    atomicAdd(&out[(size_t)tok * HDIM + col],     w * (acc[mf][nf][2] + bb0));
                    atomicAdd(&out[(size_t)tok * HDIM + col + 1], w * (acc[mf][nf][3] + bb1));
                }
            }
        }
    }
}

// ---------------- launch ----------------
extern "C" void kernel_launch(void* const* d_in, const int* in_sizes, int n_in,
                              void* d_out, int out_size) {
    const float* x  = (const float*)d_in[0];
    const float* gw = (const float*)d_in[1];
    const float* gb = (const float*)d_in[2];
    const float* w1 = (const float*)d_in[3];
    const float* b1 = (const float*)d_in[4];
    const float* w2 = (const float*)d_in[5];
    const float* b2 = (const float*)d_in[6];
    float* out = (float*)d_out;

    zero_kernel<<<(NTOK * HDIM + 255) / 256, 256>>>(out);
    gate_kernel<<<NTOK / 8, 256>>>(x, gw, gb);
    scan_kernel<<<1, 32>>>();
    scatter_kernel<<<(NTOK + 255) / 256, 256>>>();
    moe_gemm<1><<<dim3(FDIM / 128, NSLOT / 128, ENUM), 256>>>(x, w1, b1, nullptr);
    moe_gemm<2><<<dim3(HDIM / 128, NSLOT / 128, ENUM), 256>>>(nullptr, w2, b2, out);
}